// round 9
// baseline (speedup 1.0000x reference)
#include <cuda_runtime.h>
#include <math.h>

#define BB 256
#define TT 64
#define NN 128
#define MM 256
#define INROW 129   // N + YD
#define NBLK 256

typedef unsigned long long ull;

// ---------------- scratch (device globals; no allocation) ----------------
__device__ float g_Xp[BB*TT*NN];     // immutable after xp
__device__ float g_Xe[BB*TT*MM];     // immutable after encode
__device__ float g_Xd[BB*TT*MM];     // immutable after xd
__device__ float g_h[2][BB*MM];      // mutable (ldcg)
__device__ float g_c[2][BB*MM];      // mutable (ldcg)
__device__ float g_xin[BB*NN];       // mutable (ldcg)
__device__ float g_hsW[BB*MM];       // mutable (ldcg)
__device__ float g_ctx[BB*MM];
__device__ float g_yt[BB];           // mutable (ldcg)

// ---------------- grid barrier ----------------
__device__ unsigned g_bar_count;
__device__ volatile unsigned g_bar_gen;

__device__ __forceinline__ void grid_sync() {
    __syncthreads();
    __threadfence();
    if (threadIdx.x == 0) {
        unsigned gen = g_bar_gen;
        if (atomicAdd(&g_bar_count, 1) == NBLK - 1) {
            g_bar_count = 0;
            __threadfence();
            g_bar_gen = gen + 1;
        } else {
            while (g_bar_gen == gen) { __nanosleep(32); }
        }
    }
    __syncthreads();
}

// ---------------- math helpers ----------------
__device__ __forceinline__ float fast_sigm(float x) {
    return __fdividef(1.0f, 1.0f + __expf(-x));
}
__device__ __forceinline__ float fast_tanh(float x) {
    float e = __expf(2.0f * x);
    return 1.0f - __fdividef(2.0f, e + 1.0f);
}
__device__ __forceinline__ float wredsum(float v) {
    #pragma unroll
    for (int o = 16; o > 0; o >>= 1) v += __shfl_down_sync(0xffffffffu, v, o);
    return v;
}
__device__ __forceinline__ float wredmax(float v) {
    #pragma unroll
    for (int o = 16; o > 0; o >>= 1) v = fmaxf(v, __shfl_down_sync(0xffffffffu, v, o));
    return v;
}
__device__ __forceinline__ ull f2pack(float lo, float hi) {
    ull r; asm("mov.b64 %0, {%1, %2};" : "=l"(r) : "f"(lo), "f"(hi)); return r;
}
__device__ __forceinline__ void ffma2(ull& d, ull a, ull b) {
    asm("fma.rn.f32x2 %0, %1, %2, %3;" : "=l"(d) : "l"(a), "l"(b), "l"(d));
}
__device__ __forceinline__ float2 f2unpack(ull v) {
    float2 r; asm("mov.b64 {%0, %1}, %2;" : "=f"(r.x), "=f"(r.y) : "l"(v)); return r;
}
__device__ __forceinline__ void cp4(void* dst, const float* src) {
    unsigned d = (unsigned)__cvta_generic_to_shared(dst);
    asm volatile("cp.async.ca.shared.global [%0], [%1], 4;" :: "r"(d), "l"(src));
}
__device__ __forceinline__ void cp_commit() {
    asm volatile("cp.async.commit_group;" ::: "memory");
}
template <int N>
__device__ __forceinline__ void cp_wait() {
    asm volatile("cp.async.wait_group %0;" :: "n"(N) : "memory");
}

// ---------------- shared memory union ----------------
struct SmGates { float A[2][2][32][18]; float W[2][2][32][68]; float red[16][66]; };
struct SmXp    { float WUx[4096]; float Xs[8192]; };
struct SmAtt   { float hs[512]; float hsW[64]; float ves[64]; float ep[128]; float redm[4]; float reds[4]; };
struct SmHsw   { float A[2][32][20]; ull W2[2][32][21]; float red[16][18]; };
struct SmXd    { float A[32][68]; float W[32][68]; };
struct SmDatt  { float hsw[256]; float vds[256]; float l[64]; float beta[64]; float reds[8]; };
struct SmFin   { float hc[512]; float hid[256]; float reds[8]; };
union SmAll {
    SmGates g; SmXp xp; SmAtt a; SmHsw h; SmXd xd; SmDatt d; SmFin f;
};

// ---------------- phase: zero h/c ----------------
__device__ __forceinline__ void ph_init() {
    int idx = blockIdx.x * 256 + threadIdx.x;
    g_h[0][idx] = 0.f; g_h[1][idx] = 0.f;
    g_c[0][idx] = 0.f; g_c[1][idx] = 0.f;
}

// ---------------- phase: Xp precompute ----------------
__device__ __forceinline__ void ph_xp(const float* __restrict__ inp,
                                      const float* __restrict__ WU_e, SmXp& s) {
    int b = blockIdx.x, tid = threadIdx.x;
    for (int idx = tid; idx < 4096; idx += 256) {
        int t = idx >> 6, tp = idx & 63;
        s.WUx[idx] = WU_e[t*576 + 512 + tp];
    }
    for (int idx = tid; idx < 8192; idx += 256) {
        int tp = idx >> 7, n = idx & 127;
        s.Xs[idx] = inp[b*TT*INROW + tp*INROW + n];
    }
    __syncthreads();
    int half = tid >> 7, n = tid & 127;
    float acc[32];
    #pragma unroll
    for (int t = 0; t < 32; ++t) acc[t] = 0.f;
    for (int tp = 0; tp < 64; ++tp) {
        float xv = s.Xs[tp*128 + n];
        #pragma unroll
        for (int t = 0; t < 32; ++t) acc[t] += xv * s.WUx[(half*32 + t)*64 + tp];
    }
    #pragma unroll
    for (int t = 0; t < 32; ++t) g_Xp[(b*TT + half*32 + t)*NN + n] = acc[t];
}

// ---------------- phase: encoder attention ----------------
__device__ __forceinline__ void ph_enc_att(const float* __restrict__ inp,
                                           const float* __restrict__ WU_e,
                                           const float* __restrict__ v_e,
                                           int step, int par, SmAtt& s) {
    int b = blockIdx.x, tid = threadIdx.x;
    int w = tid >> 5, l = tid & 31;
    s.hs[tid]       = __ldcg(&g_h[par][b*MM + tid]);
    s.hs[tid + 256] = __ldcg(&g_c[par][b*MM + tid]);
    if (tid < 64) s.ves[tid] = v_e[tid];
    __syncthreads();
    #pragma unroll
    for (int t = w*8; t < w*8 + 8; ++t) {
        const float* row = WU_e + t*576;
        float sv = 0.f;
        #pragma unroll
        for (int k = l; k < 512; k += 32) sv += s.hs[k] * row[k];
        sv = wredsum(sv);
        if (l == 0) s.hsW[t] = sv;
    }
    __syncthreads();
    int half = tid >> 7, n = tid & 127;
    float e = 0.f;
    {
        const float* xp = g_Xp + b*TT*NN + half*32*NN + n;
        const float* vh = s.ves + half*32;
        const float* hh = s.hsW + half*32;
        #pragma unroll 8
        for (int t = 0; t < 32; ++t) e += vh[t] * fast_tanh(hh[t] + xp[t*NN]);
    }
    if (half == 1) s.ep[n] = e;
    __syncthreads();
    float p = 0.f;
    if (half == 0) {
        e += s.ep[n];
        float m = wredmax(e);
        if (l == 0) s.redm[w] = m;
    }
    __syncthreads();
    if (half == 0) {
        float m = fmaxf(fmaxf(s.redm[0], s.redm[1]), fmaxf(s.redm[2], s.redm[3]));
        p = __expf(e - m);
        float sv = wredsum(p);
        if (l == 0) s.reds[w] = sv;
    }
    __syncthreads();
    if (half == 0) {
        float tot = s.reds[0] + s.reds[1] + s.reds[2] + s.reds[3];
        float alpha = __fdividef(p, tot);
        g_xin[b*NN + n] = inp[b*TT*INROW + step*INROW + n] * alpha;
    }
}

// ---------------- phase: encoder gates GEMM + LSTM ----------------
__device__ __forceinline__ void ph_enc_gates(const float* __restrict__ Wih,
                                             const float* __restrict__ Whh,
                                             const float* __restrict__ bih,
                                             const float* __restrict__ bhh,
                                             int step, int par, SmGates& s) {
    int bb = blockIdx.x >> 4, mo = blockIdx.x & 15;
    int tid = threadIdx.x;
    int kg = tid >> 7;
    int t128 = tid & 127;
    int ty = t128 >> 4, tx = t128 & 15;
    ull acc[2][2] = {{0ull, 0ull}, {0ull, 0ull}};
    const float* hsrc = g_h[par];
    int kbase = kg * 192;
    float ra[4];

    #define ENC_LOAD_A(c) do {                                                 \
        int kc = kbase + (c)*32;                                               \
        _Pragma("unroll")                                                      \
        for (int u = 0; u < 4; ++u) {                                          \
            int idx = t128 + u*128;                                            \
            int row = idx >> 5, kk = idx & 31;                                 \
            int k = kc + kk, gb = bb*16 + row;                                 \
            ra[u] = (k < 128) ? __ldcg(g_xin + gb*NN + k)                      \
                              : __ldcg(hsrc + gb*MM + (k - 128));              \
        }                                                                      \
    } while (0)
    #define ENC_STORE_A(st) do {                                               \
        _Pragma("unroll")                                                      \
        for (int u = 0; u < 4; ++u) {                                          \
            int idx = t128 + u*128;                                            \
            s.A[st][kg][idx & 31][idx >> 5] = ra[u];                           \
        }                                                                      \
    } while (0)
    #define ENC_ISSUE_W(c, st) do {                                            \
        int kc = kbase + (c)*32;                                               \
        _Pragma("unroll")                                                      \
        for (int u = 0; u < 16; ++u) {                                         \
            int idx = t128 + u*128;                                            \
            int co = idx >> 5, kk = idx & 31;                                  \
            int row = (co >> 4)*256 + mo*16 + (co & 15);                       \
            int k = kc + kk;                                                   \
            const float* src = (k < 128) ? (Wih + row*128 + k)                 \
                                         : (Whh + row*256 + (k - 128));        \
            cp4(&s.W[st][kg][kk][co], src);                                    \
        }                                                                      \
        cp_commit();                                                           \
    } while (0)

    ENC_LOAD_A(0); ENC_ISSUE_W(0, 0); ENC_STORE_A(0);
    #pragma unroll
    for (int c = 0; c < 6; ++c) {
        int st = c & 1;
        if (c < 5) { ENC_ISSUE_W(c + 1, st ^ 1); ENC_LOAD_A(c + 1); cp_wait<1>(); }
        else       { cp_wait<0>(); }
        __syncthreads();
        #pragma unroll
        for (int kk = 0; kk < 32; ++kk) {
            float2 a = *(const float2*)&s.A[st][kg][kk][ty*2];
            ulonglong2 wv = *(const ulonglong2*)&s.W[st][kg][kk][tx*4];
            ull ax = f2pack(a.x, a.x), ay = f2pack(a.y, a.y);
            ffma2(acc[0][0], ax, wv.x); ffma2(acc[0][1], ax, wv.y);
            ffma2(acc[1][0], ay, wv.x); ffma2(acc[1][1], ay, wv.y);
        }
        if (c < 5) ENC_STORE_A(st ^ 1);
        __syncthreads();
    }
    #undef ENC_LOAD_A
    #undef ENC_STORE_A
    #undef ENC_ISSUE_W

    if (kg == 0) {
        #pragma unroll
        for (int i = 0; i < 2; ++i) {
            *(float2*)&s.red[ty*2 + i][tx*4]     = f2unpack(acc[i][0]);
            *(float2*)&s.red[ty*2 + i][tx*4 + 2] = f2unpack(acc[i][1]);
        }
    }
    __syncthreads();
    if (kg == 1) {
        #pragma unroll
        for (int i = 0; i < 2; ++i) {
            float2 v0 = f2unpack(acc[i][0]), v1 = f2unpack(acc[i][1]);
            float2 c0 = *(float2*)&s.red[ty*2 + i][tx*4];
            float2 c1 = *(float2*)&s.red[ty*2 + i][tx*4 + 2];
            c0.x += v0.x; c0.y += v0.y; c1.x += v1.x; c1.y += v1.y;
            *(float2*)&s.red[ty*2 + i][tx*4]     = c0;
            *(float2*)&s.red[ty*2 + i][tx*4 + 2] = c1;
        }
    }
    __syncthreads();
    {
        int bi = tid >> 4, ml = tid & 15;
        int gb = bb*16 + bi, m = mo*16 + ml;
        float gi = s.red[bi][ml]      + bih[m]       + bhh[m];
        float gf = s.red[bi][16 + ml] + bih[256 + m] + bhh[256 + m];
        float gg = s.red[bi][32 + ml] + bih[512 + m] + bhh[512 + m];
        float go = s.red[bi][48 + ml] + bih[768 + m] + bhh[768 + m];
        float cold = __ldcg(&g_c[par][gb*MM + m]);
        float cn = fast_sigm(gf)*cold + fast_sigm(gi)*fast_tanh(gg);
        float hn = fast_sigm(go)*fast_tanh(cn);
        g_c[par ^ 1][gb*MM + m] = cn;
        g_h[par ^ 1][gb*MM + m] = hn;
        g_Xe[(gb*TT + step)*MM + m] = hn;
    }
}

// ---------------- phase: Xd precompute (+ re-zero h/c) ----------------
__device__ __forceinline__ void ph_xd(const float* __restrict__ WU_d, SmXd& s) {
    int rb = blockIdx.x, tid = threadIdx.x;
    int ty = tid >> 4, tx = tid & 15;
    for (int ob = 0; ob < 4; ++ob) {
        float acc[4][4];
        #pragma unroll
        for (int i = 0; i < 4; ++i)
            #pragma unroll
            for (int j = 0; j < 4; ++j) acc[i][j] = 0.f;
        for (int kc = 0; kc < 256; kc += 32) {
            for (int idx = tid; idx < 2048; idx += 256) {
                int ri = idx >> 5, kk = idx & 31;
                s.A[kk][ri] = g_Xe[(rb*64 + ri)*MM + kc + kk];
            }
            for (int idx = tid; idx < 2048; idx += 256) {
                int co = idx >> 5, kk = idx & 31;
                s.W[kk][co] = WU_d[(ob*64 + co)*768 + 512 + kc + kk];
            }
            __syncthreads();
            #pragma unroll
            for (int kk = 0; kk < 32; ++kk) {
                float4 a = *(const float4*)&s.A[kk][ty*4];
                float4 w = *(const float4*)&s.W[kk][tx*4];
                acc[0][0] += a.x*w.x; acc[0][1] += a.x*w.y; acc[0][2] += a.x*w.z; acc[0][3] += a.x*w.w;
                acc[1][0] += a.y*w.x; acc[1][1] += a.y*w.y; acc[1][2] += a.y*w.z; acc[1][3] += a.y*w.w;
                acc[2][0] += a.z*w.x; acc[2][1] += a.z*w.y; acc[2][2] += a.z*w.z; acc[2][3] += a.z*w.w;
                acc[3][0] += a.w*w.x; acc[3][1] += a.w*w.y; acc[3][2] += a.w*w.z; acc[3][3] += a.w*w.w;
            }
            __syncthreads();
        }
        #pragma unroll
        for (int i = 0; i < 4; ++i)
            #pragma unroll
            for (int j = 0; j < 4; ++j)
                g_Xd[(rb*64 + ty*4 + i)*MM + ob*64 + tx*4 + j] = acc[i][j];
    }
    int idx = blockIdx.x * 256 + tid;
    g_h[0][idx] = 0.f; g_h[1][idx] = 0.f;
    g_c[0][idx] = 0.f; g_c[1][idx] = 0.f;
}

// ---------------- phase: decoder hsW GEMM ----------------
__device__ __forceinline__ void ph_dec_hsw(const float* __restrict__ WU_d, int par, SmHsw& s) {
    int rb = blockIdx.x >> 4, ob = blockIdx.x & 15;
    int tid = threadIdx.x;
    int kg = tid >> 7;
    int t128 = tid & 127;
    int ty = t128 >> 4, tx = t128 & 15;
    ull acc = 0ull;
    int kbase = kg * 256;
    for (int c = 0; c < 8; ++c) {
        int kc = kbase + c*32;
        #pragma unroll
        for (int u = 0; u < 4; ++u) {
            int idx = t128 + u*128;
            int ri = idx >> 5, kk = idx & 31;
            int k = kc + kk, gb = rb*16 + ri;
            s.A[kg][kk][ri] = (k < 256) ? __ldcg(&g_h[par][gb*MM + k])
                                        : __ldcg(&g_c[par][gb*MM + k - 256]);
        }
        #pragma unroll
        for (int u = 0; u < 4; ++u) {
            int idx = t128 + u*128;
            int co = idx >> 5, kk = idx & 31;
            float wv = WU_d[(ob*16 + co)*768 + kc + kk];
            s.W2[kg][kk][co] = f2pack(wv, wv);
        }
        __syncthreads();
        #pragma unroll
        for (int kk = 0; kk < 32; ++kk) {
            ull a = *(const ull*)&s.A[kg][kk][ty*2];
            ull w = s.W2[kg][kk][tx];
            ffma2(acc, a, w);
        }
        __syncthreads();
    }
    float2 v = f2unpack(acc);
    if (kg == 0) { s.red[ty*2][tx] = v.x; s.red[ty*2 + 1][tx] = v.y; }
    __syncthreads();
    if (kg == 1) { s.red[ty*2][tx] += v.x; s.red[ty*2 + 1][tx] += v.y; }
    __syncthreads();
    {
        int ri = tid >> 4, co = tid & 15;
        g_hsW[(rb*16 + ri)*MM + ob*16 + co] = s.red[ri][co];
    }
}

// ---------------- phase: decoder attention ----------------
__device__ __forceinline__ void ph_dec_att(const float* __restrict__ inp,
                                           const float* __restrict__ v_d,
                                           const float* __restrict__ wbt,
                                           int step, SmDatt& s) {
    int b = blockIdx.x, tid = threadIdx.x;
    int w = tid >> 5, l = tid & 31;
    s.hsw[tid] = __ldcg(&g_hsW[b*MM + tid]);
    s.vds[tid] = v_d[tid];
    __syncthreads();
    for (int t = w; t < 64; t += 8) {
        const float* xd = g_Xd + (b*TT + t)*MM;
        float sv = 0.f;
        #pragma unroll
        for (int m = l; m < 256; m += 32) sv += s.vds[m] * fast_tanh(s.hsw[m] + xd[m]);
        sv = wredsum(sv);
        if (l == 0) s.l[t] = sv;
    }
    __syncthreads();
    if (tid < 32) {
        float a0 = s.l[tid], a1 = s.l[tid + 32];
        float mx = wredmax(fmaxf(a0, a1));
        mx = __shfl_sync(0xffffffffu, mx, 0);
        float p0 = __expf(a0 - mx), p1 = __expf(a1 - mx);
        float sm2 = wredsum(p0 + p1);
        sm2 = __shfl_sync(0xffffffffu, sm2, 0);
        s.beta[tid] = __fdividef(p0, sm2);
        s.beta[tid + 32] = __fdividef(p1, sm2);
    }
    __syncthreads();
    float c = 0.f;
    const float* xe = g_Xe + b*TT*MM + tid;
    #pragma unroll 8
    for (int t = 0; t < 64; ++t) c += s.beta[t] * xe[t*MM];
    g_ctx[b*MM + tid] = c;
    float part = wbt[1 + tid] * c;
    part = wredsum(part);
    if (l == 0) s.reds[w] = part;
    __syncthreads();
    if (tid == 0) {
        float tot = 0.f;
        #pragma unroll
        for (int i = 0; i < 8; ++i) tot += s.reds[i];
        g_yt[b] = wbt[0] * inp[b*TT*INROW + step*INROW + 128] + tot;
    }
}

// ---------------- phase: decoder gates GEMM + LSTM ----------------
__device__ __forceinline__ void ph_dec_gates(const float* __restrict__ Wihd,
                                             const float* __restrict__ Whh,
                                             const float* __restrict__ bih,
                                             const float* __restrict__ bhh,
                                             int par, SmGates& s) {
    int bb = blockIdx.x >> 4, mo = blockIdx.x & 15;
    int tid = threadIdx.x;
    int kg = tid >> 7;
    int t128 = tid & 127;
    int ty = t128 >> 4, tx = t128 & 15;
    ull acc[2][2] = {{0ull, 0ull}, {0ull, 0ull}};
    const float* hsrc = g_h[par];
    int kbase = kg * 128;
    float ra[4];

    #define DEC_LOAD_A(c) do {                                                 \
        int kc = kbase + (c)*32;                                               \
        _Pragma("unroll")                                                      \
        for (int u = 0; u < 4; ++u) {                                          \
            int idx = t128 + u*128;                                            \
            int row = idx >> 5, kk = idx & 31;                                 \
            ra[u] = __ldcg(hsrc + (bb*16 + row)*MM + kc + kk);                 \
        }                                                                      \
    } while (0)
    #define DEC_STORE_A(st) do {                                               \
        _Pragma("unroll")                                                      \
        for (int u = 0; u < 4; ++u) {                                          \
            int idx = t128 + u*128;                                            \
            s.A[st][kg][idx & 31][idx >> 5] = ra[u];                           \
        }                                                                      \
    } while (0)
    #define DEC_ISSUE_W(c, st) do {                                            \
        int kc = kbase + (c)*32;                                               \
        _Pragma("unroll")                                                      \
        for (int u = 0; u < 16; ++u) {                                         \
            int idx = t128 + u*128;                                            \
            int co = idx >> 5, kk = idx & 31;                                  \
            int row = (co >> 4)*256 + mo*16 + (co & 15);                       \
            cp4(&s.W[st][kg][kk][co], Whh + row*256 + kc + kk);                \
        }                                                                      \
        cp_commit();                                                           \
    } while (0)

    DEC_LOAD_A(0); DEC_ISSUE_W(0, 0); DEC_STORE_A(0);
    #pragma unroll
    for (int c = 0; c < 4; ++c) {
        int st = c & 1;
        if (c < 3) { DEC_ISSUE_W(c + 1, st ^ 1); DEC_LOAD_A(c + 1); cp_wait<1>(); }
        else       { cp_wait<0>(); }
        __syncthreads();
        #pragma unroll
        for (int kk = 0; kk < 32; ++kk) {
            float2 a = *(const float2*)&s.A[st][kg][kk][ty*2];
            ulonglong2 wv = *(const ulonglong2*)&s.W[st][kg][kk][tx*4];
            ull ax = f2pack(a.x, a.x), ay = f2pack(a.y, a.y);
            ffma2(acc[0][0], ax, wv.x); ffma2(acc[0][1], ax, wv.y);
            ffma2(acc[1][0], ay, wv.x); ffma2(acc[1][1], ay, wv.y);
        }
        if (c < 3) DEC_STORE_A(st ^ 1);
        __syncthreads();
    }
    #undef DEC_LOAD_A
    #undef DEC_STORE_A
    #undef DEC_ISSUE_W

    if (kg == 0) {
        #pragma unroll
        for (int i = 0; i < 2; ++i) {
            *(float2*)&s.red[ty*2 + i][tx*4]     = f2unpack(acc[i][0]);
            *(float2*)&s.red[ty*2 + i][tx*4 + 2] = f2unpack(acc[i][1]);
        }
    }
    __syncthreads();
    if (kg == 1) {
        #pragma unroll
        for (int i = 0; i < 2; ++i) {
            float2 v0 = f2unpack(acc[i][0]), v1 = f2unpack(acc[i][1]);
            float2 c0 = *(float2*)&s.red[ty*2 + i][tx*4];
            float2 c1 = *(float2*)&s.red[ty*2 + i][tx*4 + 2];
            c0.x += v0.x; c0.y += v0.y; c1.x += v1.x; c1.y += v1.y;
            *(float2*)&s.red[ty*2 + i][tx*4]     = c0;
            *(float2*)&s.red[ty*2 + i][tx*4 + 2] = c1;
        }
    }
    __syncthreads();
    {
        int bi = tid >> 4, ml = tid & 15;
        int gb = bb*16 + bi, m = mo*16 + ml;
        float yt = __ldcg(&g_yt[gb]);
        float gi = s.red[bi][ml]      + bih[m]       + bhh[m]       + yt*Wihd[m];
        float gf = s.red[bi][16 + ml] + bih[256 + m] + bhh[256 + m] + yt*Wihd[256 + m];
        float gg = s.red[bi][32 + ml] + bih[512 + m] + bhh[512 + m] + yt*Wihd[512 + m];
        float go = s.red[bi][48 + ml] + bih[768 + m] + bhh[768 + m] + yt*Wihd[768 + m];
        float cold = __ldcg(&g_c[par][gb*MM + m]);
        float cn = fast_sigm(gf)*cold + fast_sigm(gi)*fast_tanh(gg);
        float hn = fast_sigm(go)*fast_tanh(cn);
        g_c[par ^ 1][gb*MM + m] = cn;
        g_h[par ^ 1][gb*MM + m] = hn;
    }
}

// ---------------- phase: final projection ----------------
__device__ __forceinline__ void ph_final(const float* __restrict__ WbW,
                                         const float* __restrict__ Wbb,
                                         const float* __restrict__ vbW,
                                         const float* __restrict__ vbb,
                                         float* __restrict__ out, int par, SmFin& s) {
    int b = blockIdx.x, tid = threadIdx.x;
    int w = tid >> 5, l = tid & 31;
    s.hc[tid]       = __ldcg(&g_h[par][b*MM + tid]);
    s.hc[256 + tid] = __ldcg(&g_ctx[b*MM + tid]);
    __syncthreads();
    for (int p = w*32; p < w*32 + 32; ++p) {
        const float* row = WbW + p*512;
        float sv = 0.f;
        #pragma unroll
        for (int k = l; k < 512; k += 32) sv += s.hc[k] * row[k];
        sv = wredsum(sv);
        if (l == 0) s.hid[p] = sv + Wbb[p];
    }
    __syncthreads();
    float part = s.hid[tid] * vbW[tid];
    part = wredsum(part);
    if (l == 0) s.reds[w] = part;
    __syncthreads();
    if (tid == 0) {
        float tot = 0.f;
        #pragma unroll
        for (int i = 0; i < 8; ++i) tot += s.reds[i];
        out[b] = tot + vbb[0];
    }
}

// ---------------- persistent megakernel ----------------
__global__ void __launch_bounds__(256, 2) k_darnn(
        const float* __restrict__ inp,  const float* __restrict__ WU_e,
        const float* __restrict__ v_e,  const float* __restrict__ Wih_e,
        const float* __restrict__ Whh_e,const float* __restrict__ bih_e,
        const float* __restrict__ bhh_e,const float* __restrict__ WU_d,
        const float* __restrict__ v_d,  const float* __restrict__ wbt,
        const float* __restrict__ Wih_d,const float* __restrict__ Whh_d,
        const float* __restrict__ bih_d,const float* __restrict__ bhh_d,
        const float* __restrict__ WbW,  const float* __restrict__ Wbb,
        const float* __restrict__ vbW,  const float* __restrict__ vbb,
        float* __restrict__ out) {
    __shared__ SmAll sm;

    ph_init();
    grid_sync();
    ph_xp(inp, WU_e, sm.xp);
    grid_sync();

    for (int s = 0; s < 64; ++s) {
        int par = s & 1;
        ph_enc_att(inp, WU_e, v_e, s, par, sm.a);
        grid_sync();
        ph_enc_gates(Wih_e, Whh_e, bih_e, bhh_e, s, par, sm.g);
        grid_sync();
    }

    ph_xd(WU_d, sm.xd);
    grid_sync();

    for (int s = 0; s < 63; ++s) {
        int par = s & 1;
        ph_dec_hsw(WU_d, par, sm.h);
        grid_sync();
        ph_dec_att(inp, v_d, wbt, s, sm.d);
        grid_sync();
        ph_dec_gates(Wih_d, Whh_d, bih_d, bhh_d, par, sm.g);
        grid_sync();
    }

    ph_final(WbW, Wbb, vbW, vbb, out, 1, sm.f);
}

// ---------------- launcher ----------------
extern "C" void kernel_launch(void* const* d_in, const int* in_sizes, int n_in,
                              void* d_out, int out_size) {
    const float* inp   = (const float*)d_in[0];
    const float* WU_e  = (const float*)d_in[1];
    const float* v_e   = (const float*)d_in[2];
    const float* Wih_e = (const float*)d_in[3];
    const float* Whh_e = (const float*)d_in[4];
    const float* bih_e = (const float*)d_in[5];
    const float* bhh_e = (const float*)d_in[6];
    const float* WU_d  = (const float*)d_in[7];
    const float* v_d   = (const float*)d_in[8];
    const float* wbt   = (const float*)d_in[9];
    const float* Wih_d = (const float*)d_in[10];
    const float* Whh_d = (const float*)d_in[11];
    const float* bih_d = (const float*)d_in[12];
    const float* bhh_d = (const float*)d_in[13];
    const float* WbW   = (const float*)d_in[14];
    const float* Wbb   = (const float*)d_in[15];
    const float* vbW   = (const float*)d_in[16];
    const float* vbb   = (const float*)d_in[17];
    float* out = (float*)d_out;

    k_darnn<<<NBLK, 256>>>(inp, WU_e, v_e, Wih_e, Whh_e, bih_e, bhh_e,
                           WU_d, v_d, wbt, Wih_d, Whh_d, bih_d, bhh_d,
                           WbW, Wbb, vbW, vbb, out);
}

// round 10
// speedup vs baseline: 1.0518x; 1.0518x over previous
#include <cuda_runtime.h>
#include <math.h>

#define BB 256
#define TT 64
#define NN 128
#define MM 256
#define INROW 129   // N + YD
#define NBLK 256

typedef unsigned long long ull;

// ---------------- scratch (device globals; no allocation) ----------------
__device__ float g_Xp[BB*TT*NN];     // immutable after xp
__device__ float g_Xe[BB*TT*MM];     // immutable after encode
__device__ float g_Xd[BB*TT*MM];     // immutable after xd
__device__ float g_h[2][BB*MM];      // mutable (ldcg)
__device__ float g_c[2][BB*MM];      // mutable (ldcg)
__device__ float g_xin[BB*NN];       // mutable (ldcg)
__device__ float g_hsW[BB*MM];       // mutable (ldcg)
__device__ float g_ctx[BB*MM];
__device__ float g_yt[BB];           // mutable (ldcg)

// ---------------- grid barrier ----------------
__device__ unsigned g_bar_count;
__device__ volatile unsigned g_bar_gen;

__device__ __forceinline__ void grid_sync() {
    __syncthreads();
    __threadfence();
    if (threadIdx.x == 0) {
        unsigned gen = g_bar_gen;
        if (atomicAdd(&g_bar_count, 1) == NBLK - 1) {
            g_bar_count = 0;
            __threadfence();
            g_bar_gen = gen + 1;
        } else {
            while (g_bar_gen == gen) { __nanosleep(32); }
        }
    }
    __syncthreads();
}

// ---------------- math helpers ----------------
__device__ __forceinline__ float fast_sigm(float x) {
    return __fdividef(1.0f, 1.0f + __expf(-x));
}
__device__ __forceinline__ float fast_tanh(float x) {
    float e = __expf(2.0f * x);
    return 1.0f - __fdividef(2.0f, e + 1.0f);
}
// single-MUFU tanh — used ONLY in attention score loops (smooth softmax path)
__device__ __forceinline__ float tanh_apx(float x) {
    float y; asm("tanh.approx.f32 %0, %1;" : "=f"(y) : "f"(x)); return y;
}
__device__ __forceinline__ float wredsum(float v) {
    #pragma unroll
    for (int o = 16; o > 0; o >>= 1) v += __shfl_down_sync(0xffffffffu, v, o);
    return v;
}
__device__ __forceinline__ float wredmax(float v) {
    #pragma unroll
    for (int o = 16; o > 0; o >>= 1) v = fmaxf(v, __shfl_down_sync(0xffffffffu, v, o));
    return v;
}
__device__ __forceinline__ ull f2pack(float lo, float hi) {
    ull r; asm("mov.b64 %0, {%1, %2};" : "=l"(r) : "f"(lo), "f"(hi)); return r;
}
__device__ __forceinline__ void ffma2(ull& d, ull a, ull b) {
    asm("fma.rn.f32x2 %0, %1, %2, %3;" : "=l"(d) : "l"(a), "l"(b), "l"(d));
}
__device__ __forceinline__ float2 f2unpack(ull v) {
    float2 r; asm("mov.b64 {%0, %1}, %2;" : "=f"(r.x), "=f"(r.y) : "l"(v)); return r;
}
__device__ __forceinline__ void cp4(void* dst, const float* src) {
    unsigned d = (unsigned)__cvta_generic_to_shared(dst);
    asm volatile("cp.async.ca.shared.global [%0], [%1], 4;" :: "r"(d), "l"(src));
}
__device__ __forceinline__ void cp_commit() {
    asm volatile("cp.async.commit_group;" ::: "memory");
}
template <int N>
__device__ __forceinline__ void cp_wait() {
    asm volatile("cp.async.wait_group %0;" :: "n"(N) : "memory");
}

// ---------------- shared memory union ----------------
struct SmGates { float A[2][2][32][18]; float W[2][2][32][68]; float red[16][66]; };
struct SmXp    { float WUx[4096]; float Xs[8192]; };
struct SmAtt   { float hs[512]; float hsW[64]; float ves[64]; float ep[128]; float redm[4]; float reds[4]; };
struct SmHsw   { float A[2][32][20]; float W[2][32][20]; float red[16][18]; };
struct SmXd    { float A[32][68]; float W[32][68]; };
struct SmDatt  { float hsw[256]; float vds[256]; float l[64]; float beta[64]; float reds[8]; };
struct SmFin   { float hc[512]; float hid[256]; float reds[8]; };
union SmAll {
    SmGates g; SmXp xp; SmAtt a; SmHsw h; SmXd xd; SmDatt d; SmFin f;
};

// ---------------- phase: Xp precompute (+ zero h/c, disjoint writes) ----------------
__device__ __forceinline__ void ph_xp(const float* __restrict__ inp,
                                      const float* __restrict__ WU_e, SmXp& s) {
    int b = blockIdx.x, tid = threadIdx.x;
    {   // init h/c (was a separate phase; writes are disjoint from xp's)
        int idx = b * 256 + tid;
        g_h[0][idx] = 0.f; g_h[1][idx] = 0.f;
        g_c[0][idx] = 0.f; g_c[1][idx] = 0.f;
    }
    for (int idx = tid; idx < 4096; idx += 256) {
        int t = idx >> 6, tp = idx & 63;
        s.WUx[idx] = WU_e[t*576 + 512 + tp];
    }
    for (int idx = tid; idx < 8192; idx += 256) {
        int tp = idx >> 7, n = idx & 127;
        s.Xs[idx] = inp[b*TT*INROW + tp*INROW + n];
    }
    __syncthreads();
    int half = tid >> 7, n = tid & 127;
    float acc[32];
    #pragma unroll
    for (int t = 0; t < 32; ++t) acc[t] = 0.f;
    for (int tp = 0; tp < 64; ++tp) {
        float xv = s.Xs[tp*128 + n];
        #pragma unroll
        for (int t = 0; t < 32; ++t) acc[t] += xv * s.WUx[(half*32 + t)*64 + tp];
    }
    #pragma unroll
    for (int t = 0; t < 32; ++t) g_Xp[(b*TT + half*32 + t)*NN + n] = acc[t];
}

// ---------------- phase: encoder attention ----------------
__device__ __forceinline__ void ph_enc_att(const float* __restrict__ inp,
                                           const float* __restrict__ WU_e,
                                           const float* __restrict__ v_e,
                                           int step, int par, SmAtt& s) {
    int b = blockIdx.x, tid = threadIdx.x;
    int w = tid >> 5, l = tid & 31;
    s.hs[tid]       = __ldcg(&g_h[par][b*MM + tid]);
    s.hs[tid + 256] = __ldcg(&g_c[par][b*MM + tid]);
    if (tid < 64) s.ves[tid] = v_e[tid];
    __syncthreads();
    #pragma unroll
    for (int t = w*8; t < w*8 + 8; ++t) {
        const float* row = WU_e + t*576;
        float sv = 0.f;
        #pragma unroll
        for (int k = l; k < 512; k += 32) sv += s.hs[k] * row[k];
        sv = wredsum(sv);
        if (l == 0) s.hsW[t] = sv;
    }
    __syncthreads();
    int half = tid >> 7, n = tid & 127;
    float e = 0.f;
    {
        const float* xp = g_Xp + b*TT*NN + half*32*NN + n;
        const float* vh = s.ves + half*32;
        const float* hh = s.hsW + half*32;
        #pragma unroll 8
        for (int t = 0; t < 32; ++t) e += vh[t] * tanh_apx(hh[t] + xp[t*NN]);
    }
    if (half == 1) s.ep[n] = e;
    __syncthreads();
    float p = 0.f;
    if (half == 0) {
        e += s.ep[n];
        float m = wredmax(e);
        if (l == 0) s.redm[w] = m;
    }
    __syncthreads();
    if (half == 0) {
        float m = fmaxf(fmaxf(s.redm[0], s.redm[1]), fmaxf(s.redm[2], s.redm[3]));
        p = __expf(e - m);
        float sv = wredsum(p);
        if (l == 0) s.reds[w] = sv;
    }
    __syncthreads();
    if (half == 0) {
        float tot = s.reds[0] + s.reds[1] + s.reds[2] + s.reds[3];
        float alpha = __fdividef(p, tot);
        g_xin[b*NN + n] = inp[b*TT*INROW + step*INROW + n] * alpha;
    }
}

// ---------------- phase: encoder gates GEMM + LSTM ----------------
__device__ __forceinline__ void ph_enc_gates(const float* __restrict__ Wih,
                                             const float* __restrict__ Whh,
                                             const float* __restrict__ bih,
                                             const float* __restrict__ bhh,
                                             int step, int par, SmGates& s) {
    int bb = blockIdx.x >> 4, mo = blockIdx.x & 15;
    int tid = threadIdx.x;
    int kg = tid >> 7;
    int t128 = tid & 127;
    int ty = t128 >> 4, tx = t128 & 15;
    ull acc[2][2] = {{0ull, 0ull}, {0ull, 0ull}};
    const float* hsrc = g_h[par];
    int kbase = kg * 192;
    float ra[4];

    #define ENC_LOAD_A(c) do {                                                 \
        int kc = kbase + (c)*32;                                               \
        _Pragma("unroll")                                                      \
        for (int u = 0; u < 4; ++u) {                                          \
            int idx = t128 + u*128;                                            \
            int row = idx >> 5, kk = idx & 31;                                 \
            int k = kc + kk, gb = bb*16 + row;                                 \
            ra[u] = (k < 128) ? __ldcg(g_xin + gb*NN + k)                      \
                              : __ldcg(hsrc + gb*MM + (k - 128));              \
        }                                                                      \
    } while (0)
    #define ENC_STORE_A(st) do {                                               \
        _Pragma("unroll")                                                      \
        for (int u = 0; u < 4; ++u) {                                          \
            int idx = t128 + u*128;                                            \
            s.A[st][kg][idx & 31][idx >> 5] = ra[u];                           \
        }                                                                      \
    } while (0)
    #define ENC_ISSUE_W(c, st) do {                                            \
        int kc = kbase + (c)*32;                                               \
        _Pragma("unroll")                                                      \
        for (int u = 0; u < 16; ++u) {                                         \
            int idx = t128 + u*128;                                            \
            int co = idx >> 5, kk = idx & 31;                                  \
            int row = (co >> 4)*256 + mo*16 + (co & 15);                       \
            int k = kc + kk;                                                   \
            const float* src = (k < 128) ? (Wih + row*128 + k)                 \
                                         : (Whh + row*256 + (k - 128));        \
            cp4(&s.W[st][kg][kk][co], src);                                    \
        }                                                                      \
        cp_commit();                                                           \
    } while (0)

    ENC_LOAD_A(0); ENC_ISSUE_W(0, 0); ENC_STORE_A(0);
    #pragma unroll
    for (int c = 0; c < 6; ++c) {
        int st = c & 1;
        if (c < 5) { ENC_ISSUE_W(c + 1, st ^ 1); ENC_LOAD_A(c + 1); cp_wait<1>(); }
        else       { cp_wait<0>(); }
        __syncthreads();
        #pragma unroll
        for (int kk = 0; kk < 32; ++kk) {
            float2 a = *(const float2*)&s.A[st][kg][kk][ty*2];
            float4 w = *(const float4*)&s.W[st][kg][kk][tx*4];
            ull ax = f2pack(a.x, a.x), ay = f2pack(a.y, a.y);
            ull w01 = f2pack(w.x, w.y), w23 = f2pack(w.z, w.w);
            ffma2(acc[0][0], ax, w01); ffma2(acc[0][1], ax, w23);
            ffma2(acc[1][0], ay, w01); ffma2(acc[1][1], ay, w23);
        }
        if (c < 5) ENC_STORE_A(st ^ 1);
        __syncthreads();
    }
    #undef ENC_LOAD_A
    #undef ENC_STORE_A
    #undef ENC_ISSUE_W

    if (kg == 0) {
        #pragma unroll
        for (int i = 0; i < 2; ++i) {
            *(float2*)&s.red[ty*2 + i][tx*4]     = f2unpack(acc[i][0]);
            *(float2*)&s.red[ty*2 + i][tx*4 + 2] = f2unpack(acc[i][1]);
        }
    }
    __syncthreads();
    if (kg == 1) {
        #pragma unroll
        for (int i = 0; i < 2; ++i) {
            float2 v0 = f2unpack(acc[i][0]), v1 = f2unpack(acc[i][1]);
            float2 c0 = *(float2*)&s.red[ty*2 + i][tx*4];
            float2 c1 = *(float2*)&s.red[ty*2 + i][tx*4 + 2];
            c0.x += v0.x; c0.y += v0.y; c1.x += v1.x; c1.y += v1.y;
            *(float2*)&s.red[ty*2 + i][tx*4]     = c0;
            *(float2*)&s.red[ty*2 + i][tx*4 + 2] = c1;
        }
    }
    __syncthreads();
    {
        int bi = tid >> 4, ml = tid & 15;
        int gb = bb*16 + bi, m = mo*16 + ml;
        float gi = s.red[bi][ml]      + bih[m]       + bhh[m];
        float gf = s.red[bi][16 + ml] + bih[256 + m] + bhh[256 + m];
        float gg = s.red[bi][32 + ml] + bih[512 + m] + bhh[512 + m];
        float go = s.red[bi][48 + ml] + bih[768 + m] + bhh[768 + m];
        float cold = __ldcg(&g_c[par][gb*MM + m]);
        float cn = fast_sigm(gf)*cold + fast_sigm(gi)*fast_tanh(gg);
        float hn = fast_sigm(go)*fast_tanh(cn);
        g_c[par ^ 1][gb*MM + m] = cn;
        g_h[par ^ 1][gb*MM + m] = hn;
        g_Xe[(gb*TT + step)*MM + m] = hn;
    }
}

// ---------------- phase: Xd precompute (+ re-zero h/c) ----------------
__device__ __forceinline__ void ph_xd(const float* __restrict__ WU_d, SmXd& s) {
    int rb = blockIdx.x, tid = threadIdx.x;
    int ty = tid >> 4, tx = tid & 15;
    for (int ob = 0; ob < 4; ++ob) {
        float acc[4][4];
        #pragma unroll
        for (int i = 0; i < 4; ++i)
            #pragma unroll
            for (int j = 0; j < 4; ++j) acc[i][j] = 0.f;
        for (int kc = 0; kc < 256; kc += 32) {
            for (int idx = tid; idx < 2048; idx += 256) {
                int ri = idx >> 5, kk = idx & 31;
                s.A[kk][ri] = g_Xe[(rb*64 + ri)*MM + kc + kk];
            }
            for (int idx = tid; idx < 2048; idx += 256) {
                int co = idx >> 5, kk = idx & 31;
                s.W[kk][co] = WU_d[(ob*64 + co)*768 + 512 + kc + kk];
            }
            __syncthreads();
            #pragma unroll
            for (int kk = 0; kk < 32; ++kk) {
                float4 a = *(const float4*)&s.A[kk][ty*4];
                float4 w = *(const float4*)&s.W[kk][tx*4];
                acc[0][0] += a.x*w.x; acc[0][1] += a.x*w.y; acc[0][2] += a.x*w.z; acc[0][3] += a.x*w.w;
                acc[1][0] += a.y*w.x; acc[1][1] += a.y*w.y; acc[1][2] += a.y*w.z; acc[1][3] += a.y*w.w;
                acc[2][0] += a.z*w.x; acc[2][1] += a.z*w.y; acc[2][2] += a.z*w.z; acc[2][3] += a.z*w.w;
                acc[3][0] += a.w*w.x; acc[3][1] += a.w*w.y; acc[3][2] += a.w*w.z; acc[3][3] += a.w*w.w;
            }
            __syncthreads();
        }
        #pragma unroll
        for (int i = 0; i < 4; ++i)
            #pragma unroll
            for (int j = 0; j < 4; ++j)
                g_Xd[(rb*64 + ty*4 + i)*MM + ob*64 + tx*4 + j] = acc[i][j];
    }
    int idx = blockIdx.x * 256 + tid;
    g_h[0][idx] = 0.f; g_h[1][idx] = 0.f;
    g_c[0][idx] = 0.f; g_c[1][idx] = 0.f;
}

// ---------------- phase: decoder hsW GEMM ----------------
__device__ __forceinline__ void ph_dec_hsw(const float* __restrict__ WU_d, int par, SmHsw& s) {
    int rb = blockIdx.x >> 4, ob = blockIdx.x & 15;
    int tid = threadIdx.x;
    int kg = tid >> 7;
    int t128 = tid & 127;
    int ty = t128 >> 4, tx = t128 & 15;
    ull acc = 0ull;
    int kbase = kg * 256;
    for (int c = 0; c < 8; ++c) {
        int kc = kbase + c*32;
        #pragma unroll
        for (int u = 0; u < 4; ++u) {
            int idx = t128 + u*128;
            int ri = idx >> 5, kk = idx & 31;
            int k = kc + kk, gb = rb*16 + ri;
            s.A[kg][kk][ri] = (k < 256) ? __ldcg(&g_h[par][gb*MM + k])
                                        : __ldcg(&g_c[par][gb*MM + k - 256]);
        }
        #pragma unroll
        for (int u = 0; u < 4; ++u) {
            int idx = t128 + u*128;
            int co = idx >> 5, kk = idx & 31;
            s.W[kg][kk][co] = WU_d[(ob*16 + co)*768 + kc + kk];
        }
        __syncthreads();
        #pragma unroll
        for (int kk = 0; kk < 32; ++kk) {
            float2 a = *(const float2*)&s.A[kg][kk][ty*2];
            float w = s.W[kg][kk][tx];
            ffma2(acc, f2pack(a.x, a.y), f2pack(w, w));
        }
        __syncthreads();
    }
    float2 v = f2unpack(acc);
    if (kg == 0) { s.red[ty*2][tx] = v.x; s.red[ty*2 + 1][tx] = v.y; }
    __syncthreads();
    if (kg == 1) { s.red[ty*2][tx] += v.x; s.red[ty*2 + 1][tx] += v.y; }
    __syncthreads();
    {
        int ri = tid >> 4, co = tid & 15;
        g_hsW[(rb*16 + ri)*MM + ob*16 + co] = s.red[ri][co];
    }
}

// ---------------- phase: decoder attention ----------------
__device__ __forceinline__ void ph_dec_att(const float* __restrict__ inp,
                                           const float* __restrict__ v_d,
                                           const float* __restrict__ wbt,
                                           int step, SmDatt& s) {
    int b = blockIdx.x, tid = threadIdx.x;
    int w = tid >> 5, l = tid & 31;
    s.hsw[tid] = __ldcg(&g_hsW[b*MM + tid]);
    s.vds[tid] = v_d[tid];
    __syncthreads();
    for (int t = w; t < 64; t += 8) {
        const float* xd = g_Xd + (b*TT + t)*MM;
        float sv = 0.f;
        #pragma unroll
        for (int m = l; m < 256; m += 32) sv += s.vds[m] * tanh_apx(s.hsw[m] + xd[m]);
        sv = wredsum(sv);
        if (l == 0) s.l[t] = sv;
    }
    __syncthreads();
    if (tid < 32) {
        float a0 = s.l[tid], a1 = s.l[tid + 32];
        float mx = wredmax(fmaxf(a0, a1));
        mx = __shfl_sync(0xffffffffu, mx, 0);
        float p0 = __expf(a0 - mx), p1 = __expf(a1 - mx);
        float sm2 = wredsum(p0 + p1);
        sm2 = __shfl_sync(0xffffffffu, sm2, 0);
        s.beta[tid] = __fdividef(p0, sm2);
        s.beta[tid + 32] = __fdividef(p1, sm2);
    }
    __syncthreads();
    float c = 0.f;
    const float* xe = g_Xe + b*TT*MM + tid;
    #pragma unroll 8
    for (int t = 0; t < 64; ++t) c += s.beta[t] * xe[t*MM];
    g_ctx[b*MM + tid] = c;
    float part = wbt[1 + tid] * c;
    part = wredsum(part);
    if (l == 0) s.reds[w] = part;
    __syncthreads();
    if (tid == 0) {
        float tot = 0.f;
        #pragma unroll
        for (int i = 0; i < 8; ++i) tot += s.reds[i];
        g_yt[b] = wbt[0] * inp[b*TT*INROW + step*INROW + 128] + tot;
    }
}

// ---------------- phase: decoder gates GEMM + LSTM ----------------
__device__ __forceinline__ void ph_dec_gates(const float* __restrict__ Wihd,
                                             const float* __restrict__ Whh,
                                             const float* __restrict__ bih,
                                             const float* __restrict__ bhh,
                                             int par, SmGates& s) {
    int bb = blockIdx.x >> 4, mo = blockIdx.x & 15;
    int tid = threadIdx.x;
    int kg = tid >> 7;
    int t128 = tid & 127;
    int ty = t128 >> 4, tx = t128 & 15;
    ull acc[2][2] = {{0ull, 0ull}, {0ull, 0ull}};
    const float* hsrc = g_h[par];
    int kbase = kg * 128;
    float ra[4];

    #define DEC_LOAD_A(c) do {                                                 \
        int kc = kbase + (c)*32;                                               \
        _Pragma("unroll")                                                      \
        for (int u = 0; u < 4; ++u) {                                          \
            int idx = t128 + u*128;                                            \
            int row = idx >> 5, kk = idx & 31;                                 \
            ra[u] = __ldcg(hsrc + (bb*16 + row)*MM + kc + kk);                 \
        }                                                                      \
    } while (0)
    #define DEC_STORE_A(st) do {                                               \
        _Pragma("unroll")                                                      \
        for (int u = 0; u < 4; ++u) {                                          \
            int idx = t128 + u*128;                                            \
            s.A[st][kg][idx & 31][idx >> 5] = ra[u];                           \
        }                                                                      \
    } while (0)
    #define DEC_ISSUE_W(c, st) do {                                            \
        int kc = kbase + (c)*32;                                               \
        _Pragma("unroll")                                                      \
        for (int u = 0; u < 16; ++u) {                                         \
            int idx = t128 + u*128;                                            \
            int co = idx >> 5, kk = idx & 31;                                  \
            int row = (co >> 4)*256 + mo*16 + (co & 15);                       \
            cp4(&s.W[st][kg][kk][co], Whh + row*256 + kc + kk);                \
        }                                                                      \
        cp_commit();                                                           \
    } while (0)

    DEC_LOAD_A(0); DEC_ISSUE_W(0, 0); DEC_STORE_A(0);
    #pragma unroll
    for (int c = 0; c < 4; ++c) {
        int st = c & 1;
        if (c < 3) { DEC_ISSUE_W(c + 1, st ^ 1); DEC_LOAD_A(c + 1); cp_wait<1>(); }
        else       { cp_wait<0>(); }
        __syncthreads();
        #pragma unroll
        for (int kk = 0; kk < 32; ++kk) {
            float2 a = *(const float2*)&s.A[st][kg][kk][ty*2];
            float4 w = *(const float4*)&s.W[st][kg][kk][tx*4];
            ull ax = f2pack(a.x, a.x), ay = f2pack(a.y, a.y);
            ull w01 = f2pack(w.x, w.y), w23 = f2pack(w.z, w.w);
            ffma2(acc[0][0], ax, w01); ffma2(acc[0][1], ax, w23);
            ffma2(acc[1][0], ay, w01); ffma2(acc[1][1], ay, w23);
        }
        if (c < 3) DEC_STORE_A(st ^ 1);
        __syncthreads();
    }
    #undef DEC_LOAD_A
    #undef DEC_STORE_A
    #undef DEC_ISSUE_W

    if (kg == 0) {
        #pragma unroll
        for (int i = 0; i < 2; ++i) {
            *(float2*)&s.red[ty*2 + i][tx*4]     = f2unpack(acc[i][0]);
            *(float2*)&s.red[ty*2 + i][tx*4 + 2] = f2unpack(acc[i][1]);
        }
    }
    __syncthreads();
    if (kg == 1) {
        #pragma unroll
        for (int i = 0; i < 2; ++i) {
            float2 v0 = f2unpack(acc[i][0]), v1 = f2unpack(acc[i][1]);
            float2 c0 = *(float2*)&s.red[ty*2 + i][tx*4];
            float2 c1 = *(float2*)&s.red[ty*2 + i][tx*4 + 2];
            c0.x += v0.x; c0.y += v0.y; c1.x += v1.x; c1.y += v1.y;
            *(float2*)&s.red[ty*2 + i][tx*4]     = c0;
            *(float2*)&s.red[ty*2 + i][tx*4 + 2] = c1;
        }
    }
    __syncthreads();
    {
        int bi = tid >> 4, ml = tid & 15;
        int gb = bb*16 + bi, m = mo*16 + ml;
        float yt = __ldcg(&g_yt[gb]);
        float gi = s.red[bi][ml]      + bih[m]       + bhh[m]       + yt*Wihd[m];
        float gf = s.red[bi][16 + ml] + bih[256 + m] + bhh[256 + m] + yt*Wihd[256 + m];
        float gg = s.red[bi][32 + ml] + bih[512 + m] + bhh[512 + m] + yt*Wihd[512 + m];
        float go = s.red[bi][48 + ml] + bih[768 + m] + bhh[768 + m] + yt*Wihd[768 + m];
        float cold = __ldcg(&g_c[par][gb*MM + m]);
        float cn = fast_sigm(gf)*cold + fast_sigm(gi)*fast_tanh(gg);
        float hn = fast_sigm(go)*fast_tanh(cn);
        g_c[par ^ 1][gb*MM + m] = cn;
        g_h[par ^ 1][gb*MM + m] = hn;
    }
}

// ---------------- phase: final projection ----------------
__device__ __forceinline__ void ph_final(const float* __restrict__ WbW,
                                         const float* __restrict__ Wbb,
                                         const float* __restrict__ vbW,
                                         const float* __restrict__ vbb,
                                         float* __restrict__ out, int par, SmFin& s) {
    int b = blockIdx.x, tid = threadIdx.x;
    int w = tid >> 5, l = tid & 31;
    s.hc[tid]       = __ldcg(&g_h[par][b*MM + tid]);
    s.hc[256 + tid] = __ldcg(&g_ctx[b*MM + tid]);
    __syncthreads();
    for (int p = w*32; p < w*32 + 32; ++p) {
        const float* row = WbW + p*512;
        float sv = 0.f;
        #pragma unroll
        for (int k = l; k < 512; k += 32) sv += s.hc[k] * row[k];
        sv = wredsum(sv);
        if (l == 0) s.hid[p] = sv + Wbb[p];
    }
    __syncthreads();
    float part = s.hid[tid] * vbW[tid];
    part = wredsum(part);
    if (l == 0) s.reds[w] = part;
    __syncthreads();
    if (tid == 0) {
        float tot = 0.f;
        #pragma unroll
        for (int i = 0; i < 8; ++i) tot += s.reds[i];
        out[b] = tot + vbb[0];
    }
}

// ---------------- persistent megakernel ----------------
__global__ void __launch_bounds__(256, 2) k_darnn(
        const float* __restrict__ inp,  const float* __restrict__ WU_e,
        const float* __restrict__ v_e,  const float* __restrict__ Wih_e,
        const float* __restrict__ Whh_e,const float* __restrict__ bih_e,
        const float* __restrict__ bhh_e,const float* __restrict__ WU_d,
        const float* __restrict__ v_d,  const float* __restrict__ wbt,
        const float* __restrict__ Wih_d,const float* __restrict__ Whh_d,
        const float* __restrict__ bih_d,const float* __restrict__ bhh_d,
        const float* __restrict__ WbW,  const float* __restrict__ Wbb,
        const float* __restrict__ vbW,  const float* __restrict__ vbb,
        float* __restrict__ out) {
    __shared__ SmAll sm;

    ph_xp(inp, WU_e, sm.xp);
    grid_sync();

    for (int s = 0; s < 64; ++s) {
        int par = s & 1;
        ph_enc_att(inp, WU_e, v_e, s, par, sm.a);
        grid_sync();
        ph_enc_gates(Wih_e, Whh_e, bih_e, bhh_e, s, par, sm.g);
        grid_sync();
    }

    ph_xd(WU_d, sm.xd);
    grid_sync();

    for (int s = 0; s < 63; ++s) {
        int par = s & 1;
        ph_dec_hsw(WU_d, par, sm.h);
        grid_sync();
        ph_dec_att(inp, v_d, wbt, s, sm.d);
        grid_sync();
        ph_dec_gates(Wih_d, Whh_d, bih_d, bhh_d, par, sm.g);
        grid_sync();
    }

    ph_final(WbW, Wbb, vbW, vbb, out, 1, sm.f);
}

// ---------------- launcher ----------------
extern "C" void kernel_launch(void* const* d_in, const int* in_sizes, int n_in,
                              void* d_out, int out_size) {
    const float* inp   = (const float*)d_in[0];
    const float* WU_e  = (const float*)d_in[1];
    const float* v_e   = (const float*)d_in[2];
    const float* Wih_e = (const float*)d_in[3];
    const float* Whh_e = (const float*)d_in[4];
    const float* bih_e = (const float*)d_in[5];
    const float* bhh_e = (const float*)d_in[6];
    const float* WU_d  = (const float*)d_in[7];
    const float* v_d   = (const float*)d_in[8];
    const float* wbt   = (const float*)d_in[9];
    const float* Wih_d = (const float*)d_in[10];
    const float* Whh_d = (const float*)d_in[11];
    const float* bih_d = (const float*)d_in[12];
    const float* bhh_d = (const float*)d_in[13];
    const float* WbW   = (const float*)d_in[14];
    const float* Wbb   = (const float*)d_in[15];
    const float* vbW   = (const float*)d_in[16];
    const float* vbb   = (const float*)d_in[17];
    float* out = (float*)d_out;

    k_darnn<<<NBLK, 256>>>(inp, WU_e, v_e, Wih_e, Whh_e, bih_e, bhh_e,
                           WU_d, v_d, wbt, Wih_d, Whh_d, bih_d, bhh_d,
                           WbW, Wbb, vbW, vbb, out);
}